// round 4
// baseline (speedup 1.0000x reference)
#include <cuda_runtime.h>

#define MAXROWS 8192
#define NT      512
#define NW      (NT / 32)           // 16 warps
#define SLOTS   20                  // per-thread candidate slots (interleaved layout)

__device__ float g_rowloss[MAXROWS];

__device__ __forceinline__ float warpReduceSum(float v) {
#pragma unroll
    for (int o = 16; o; o >>= 1) v += __shfl_down_sync(0xffffffffu, v, o);
    return v;
}

// Returns the block sum to ALL threads (each thread sums the NW warp partials
// in the same fixed order -> deterministic and uniform).
__device__ __forceinline__ float blockReduceSumAll(float v, float* sbuf) {
    int lane = threadIdx.x & 31, warp = threadIdx.x >> 5;
    v = warpReduceSum(v);
    __syncthreads();                     // protect sbuf from previous round
    if (lane == 0) sbuf[warp] = v;
    __syncthreads();
    float s = 0.f;
#pragma unroll
    for (int w = 0; w < NW; w++) s += sbuf[w];
    return s;
}

// Robust target load: auto-detect int32 vs int64 storage (int64 -> odd words zero).
__device__ __forceinline__ int load_target(const void* tgt, int row, int n, int d) {
    const int* t32 = (const int*)tgt;
    int lim = (n < 32) ? n : 32;
    bool is64 = true;
    for (int i = 0; i < lim; i++) is64 = is64 && (t32[2 * i + 1] == 0);
    long long v = is64 ? ((const long long*)tgt)[row] : (long long)t32[row];
    int t = (int)v;
    if (t < 0 || t >= d) t = 0;
    return t;
}

__global__ __launch_bounds__(NT) void tsallis_kernel(const float* __restrict__ in,
                                                     const void* __restrict__ tgt,
                                                     int d, int n) {
    int row  = blockIdx.x;
    int tid  = threadIdx.x;
    int lane = tid & 31, warp = tid >> 5;
    const float* xr = in + (size_t)row * d;

    __shared__ float cand[SLOTS * NT];   // 40 KB, slot j of thread t at [j*NT + t]
    __shared__ float sred[NW];
    __shared__ int   s_ovf;

    if (tid == 0) s_ovf = 0;

    int  nf4     = d >> 2;
    bool generic = (d & 3) != 0;

    float cm = -3.4e38f;     // thread-local running max (input units)
    int   c  = 0;            // per-thread kept count

    if (!generic) {
        const float4* p4 = (const float4*)xr;

        // ---- Prologue: block max of first NT float4s -> initial threshold ----
        float lm = -3.4e38f;
        if (tid < nf4) {
            float4 v = p4[tid];
            lm = fmaxf(fmaxf(v.x, v.y), fmaxf(v.z, v.w));
        }
#pragma unroll
        for (int o = 16; o; o >>= 1) lm = fmaxf(lm, __shfl_xor_sync(0xffffffffu, lm, o));
        if (lane == 0) sred[warp] = lm;
        __syncthreads();
        float bm = sred[0];
#pragma unroll
        for (int w = 1; w < NW; w++) bm = fmaxf(bm, sred[w]);
        cm = bm;
        float th = cm - 2.0f;            // input units: x > max_in - 2  <=>  X > maxX - 1
        __syncthreads();                 // sred reused later

        // ---- Main streaming pass: chunks of 8 float4s per thread ----
        int nch = (nf4 + 8 * NT - 1) / (8 * NT);     // uniform across block
        for (int k = 0; k < nch; k++) {
            float lm2 = -3.4e38f;
#pragma unroll
            for (int u = 0; u < 8; u++) {
                int idx = (k * 8 + u) * NT + tid;
                if (idx < nf4) {
                    float4 v = p4[idx];
                    lm2 = fmaxf(lm2, fmaxf(fmaxf(v.x, v.y), fmaxf(v.z, v.w)));
                    // On overflow we clobber the last slot; the row falls to the
                    // slow path anyway, so the data is never used.
                    if (v.x > th) { cand[(c < SLOTS ? c : SLOTS - 1) * NT + tid] = 0.5f * v.x; c++; }
                    if (v.y > th) { cand[(c < SLOTS ? c : SLOTS - 1) * NT + tid] = 0.5f * v.y; c++; }
                    if (v.z > th) { cand[(c < SLOTS ? c : SLOTS - 1) * NT + tid] = 0.5f * v.z; c++; }
                    if (v.w > th) { cand[(c < SLOTS ? c : SLOTS - 1) * NT + tid] = 0.5f * v.w; c++; }
                }
            }
            // Refresh threshold once per chunk (warp-level, stale-but-monotone).
            cm = fmaxf(cm, lm2);
            float t2 = cm;
#pragma unroll
            for (int o = 16; o; o >>= 1) t2 = fmaxf(t2, __shfl_xor_sync(0xffffffffu, t2, o));
            cm = t2;
            th = cm - 2.0f;
        }
    } else {
        // Unusual shape: exact max only, force slow path.
        float m = -3.4e38f;
        for (int i = tid; i < d; i += NT) m = fmaxf(m, xr[i]);
        cm = m;
        if (tid == 0) s_ovf = 1;
    }

    if (c > SLOTS) atomicOr(&s_ovf, 1);

    // ---- Exact block max -> maxX ----
#pragma unroll
    for (int o = 16; o; o >>= 1) cm = fmaxf(cm, __shfl_xor_sync(0xffffffffu, cm, o));
    if (lane == 0) sred[warp] = cm;
    __syncthreads();
    float bm2 = sred[0];
#pragma unroll
    for (int w = 1; w < NW; w++) bm2 = fmaxf(bm2, sred[w]);
    bool  slow   = (s_ovf != 0);
    float maxX   = 0.5f * bm2;
    float tau_lo = maxX - 1.0f;
    float tau_hi = maxX - (float)(1.0 / sqrt((double)d));   // maxX - (1/d)^(alpha-1)
    int   myc    = slow ? 0 : c;

    // ---- f_lo ----
    float fl = 0.f;
    if (!slow) {
        for (int j = 0; j < myc; j++) {
            float t = cand[j * NT + tid] - tau_lo;
            if (t > 0.f) fl = fmaf(t, t, fl);
        }
    } else {
        for (int i = tid; i < d; i += NT) {
            float t = fmaxf(0.5f * __ldg(xr + i) - tau_lo, 0.f);
            fl = fmaf(t, t, fl);
        }
    }
    float f_lo = blockReduceSumAll(fl, sred) - 1.0f;

    // ---- 15 bisection iterations ----
    float dm    = tau_hi - tau_lo;
    float tau_m = tau_lo;
#pragma unroll 1
    for (int it = 0; it < 15; it++) {
        dm *= 0.5f;
        tau_m = tau_lo + dm;
        float s = 0.f;
        if (!slow) {
            for (int j = 0; j < myc; j++) {
                float t = fmaxf(cand[j * NT + tid] - tau_m, 0.f);
                s = fmaf(t, t, s);
            }
        } else {
            for (int i = tid; i < d; i += NT) {
                float t = fmaxf(0.5f * __ldg(xr + i) - tau_m, 0.f);
                s = fmaf(t, t, s);
            }
        }
        float fm = blockReduceSumAll(s, sred) - 1.0f;
        tau_lo = (fm * f_lo >= 0.f) ? tau_m : tau_lo;   // uniform across block
    }

    // ---- Finals at last tau_m: S3 = sum t^3, PX = sum p*X ----
    float s3 = 0.f, px = 0.f;
    if (!slow) {
        for (int j = 0; j < myc; j++) {
            float x = cand[j * NT + tid];
            float t = fmaxf(x - tau_m, 0.f);
            float p = t * t;
            s3 = fmaf(p, t, s3);
            px = fmaf(p, x, px);
        }
    } else {
        for (int i = tid; i < d; i += NT) {
            float x = 0.5f * __ldg(xr + i);
            float t = fmaxf(x - tau_m, 0.f);
            float p = t * t;
            s3 = fmaf(p, t, s3);
            px = fmaf(p, x, px);
        }
    }
    float S3 = blockReduceSumAll(s3, sred);
    float PX = blockReduceSumAll(px, sred);
    if (tid == 0) {
        int t = load_target(tgt, row, n, d);
        float xt = __ldg(xr + t);
        // loss = (1 - S3)/(alpha*(alpha-1)) + sum(p*input) - input[target]
        //      = (1 - S3)/0.75 + 2*PX - xt        (input = 2*X)
        g_rowloss[row] = (1.0f - S3) / 0.75f + 2.0f * PX - xt;
    }
}

// Deterministic mean over rows
__global__ __launch_bounds__(1024) void reduce_kernel(float* __restrict__ out, int n) {
    __shared__ float sbuf[32];
    float s = 0.f;
    int n4 = n >> 2;
    const float4* p4 = (const float4*)g_rowloss;
    for (int i = threadIdx.x; i < n4; i += 1024) {
        float4 v = p4[i];
        s += (v.x + v.y) + (v.z + v.w);
    }
    for (int i = (n4 << 2) + threadIdx.x; i < n; i += 1024) s += g_rowloss[i];
    s = warpReduceSum(s);
    if ((threadIdx.x & 31) == 0) sbuf[threadIdx.x >> 5] = s;
    __syncthreads();
    if (threadIdx.x < 32) {
        float x = sbuf[threadIdx.x];
        x = warpReduceSum(x);
        if (threadIdx.x == 0) out[0] = x / (float)n;
    }
}

extern "C" void kernel_launch(void* const* d_in, const int* in_sizes, int n_in,
                              void* d_out, int out_size) {
    // Pick logits vs targets by size: the big buffer is the [n, d] logits.
    int idx_in = 0, idx_tg = 1;
    if (n_in >= 2 && in_sizes[1] > in_sizes[0]) { idx_in = 1; idx_tg = 0; }
    const float* in  = (const float*)d_in[idx_in];
    const void*  tgt = d_in[idx_tg];

    int n = in_sizes[idx_tg];
    if (n <= 0) n = 1;
    int d = in_sizes[idx_in] / n;
    if (n > MAXROWS) n = MAXROWS;   // shapes fixed: 4096 x 32000

    tsallis_kernel<<<n, NT>>>(in, tgt, d, n);
    reduce_kernel<<<1, 1024>>>((float*)d_out, n);
}